// round 10
// baseline (speedup 1.0000x reference)
#include <cuda_runtime.h>
#include <cuda_fp16.h>
#include <mma.h>
#include <cstdint>
using namespace nvcuda;

// Problem constants (fixed by setup_inputs)
#define BATCH   32
#define SLEN    4096
#define DMODEL  512
#define NHEADS  8
#define HD      64
#define WIN     128
#define SHIFT   64
#define NWIN    1024          // total windows (BATCH * 32)

// ---------------------------------------------------------------------------
// Persistent fp16 arrays (all hi-only; calibrated rel_err ~7e-4)
// ---------------------------------------------------------------------------
__device__ __align__(16) __half g_x_hi[(size_t)BATCH * SLEN * DMODEL];
__device__ __align__(16) __half g_win_hi[3 * DMODEL * DMODEL];
__device__ __align__(16) __half g_wout_hi[DMODEL * DMODEL];
__device__ __align__(16) __half g_o_hi[(size_t)NWIN * WIN * DMODEL];

// ---------------------------------------------------------------------------
// wmma fp16 types
// ---------------------------------------------------------------------------
using HA  = wmma::fragment<wmma::matrix_a, 16, 16, 16, __half, wmma::row_major>;
using HBc = wmma::fragment<wmma::matrix_b, 16, 16, 16, __half, wmma::col_major>;
using HBr = wmma::fragment<wmma::matrix_b, 16, 16, 16, __half, wmma::row_major>;
using CF  = wmma::fragment<wmma::accumulator, 16, 16, 16, float>;

__device__ __forceinline__ void hi_store4(const float4 v, __half* hi) {
    *reinterpret_cast<__half2*>(hi)     = __halves2half2(__float2half_rn(v.x), __float2half_rn(v.y));
    *reinterpret_cast<__half2*>(hi + 2) = __halves2half2(__float2half_rn(v.z), __float2half_rn(v.w));
}

// ---------------------------------------------------------------------------
// cp.async helpers
// ---------------------------------------------------------------------------
__device__ __forceinline__ uint32_t smem_to_u32(const void* p) {
    uint32_t a;
    asm("{ .reg .u64 t; cvta.to.shared.u64 t, %1; cvt.u32.u64 %0, t; }" : "=r"(a) : "l"(p));
    return a;
}
#define CP_ASYNC16(su32, gptr) \
    asm volatile("cp.async.cg.shared.global [%0], [%1], 16;" :: "r"(su32), "l"(gptr) : "memory")
#define CP_COMMIT() asm volatile("cp.async.commit_group;" ::: "memory")
#define CP_WAIT(n)  asm volatile("cp.async.wait_group %0;" :: "n"(n) : "memory")

// ---------------------------------------------------------------------------
// Prep splits. which: 0 = x, 1 = w_in, 2 = w_out
// ---------------------------------------------------------------------------
__global__ void k_split(const float4* __restrict__ src, int which, int n4) {
    int i = blockIdx.x * blockDim.x + threadIdx.x;
    if (i >= n4) return;
    float4 v = src[i];
    if (which == 0)      hi_store4(v, g_x_hi + (size_t)i * 4);
    else if (which == 1) hi_store4(v, g_win_hi + (size_t)i * 4);
    else                 hi_store4(v, g_wout_hi + (size_t)i * 4);
}

// ---------------------------------------------------------------------------
// FUSED QKV-projection + attention. One CTA per (head, window), 512 threads.
//
// Phase 1: QKV_h[128,192] = x_w[128,512] @ w_in_h[192,512]^T (+bias), cp.async
//          2-stage, warp grid 4x4, warp tile 32x48. Q scaled by 0.125 (exact).
//          Output written as fp16 into smem Qh/Kh/Vh.
// Phase 2: S = Qh @ Kh^T (scale pre-applied), 4x4 grid, 32x32 tiles.
// Phase 3: softmax (16 warps x 8 rows), P -> fp16 Ph.
// Phase 4: O = Ph @ Vh, 8x2 grid, 16x32 tiles -> g_o_hi.
//
// smem map (bytes):
//   region0 [0, 102400): union of
//     - 2 GEMM stages @ 46080 (A[128][72] fp16 +0, B[192][72] fp16 +18432)
//     - Cs fp32 [128][200] (102400)
//     - Ps fp32 [128][132] (67584)
//     - Os fp32 [128][68]  (34816)
//   Qh [128][72] fp16 @ 102400
//   Kh [128][72] fp16 @ 120832
//   Vh [128][72] fp16 @ 139264
//   Ph [128][136] fp16 @ 157696  (end 192512)
// ---------------------------------------------------------------------------
#define FSTG 46080
#define FUSED_SMEM 192512

__global__ __launch_bounds__(512, 1) void k_fused(const float* __restrict__ b_in) {
    extern __shared__ char smem[];
    const uint32_t sb0 = smem_to_u32(smem);
    float*  Cs = (float*)smem;                       // [128][200]
    float*  Ps = (float*)smem;                       // [128][132]
    float*  Os = (float*)smem;                       // [128][68]
    __half* Qh = (__half*)(smem + 102400);           // [128][72]
    __half* Kh = (__half*)(smem + 120832);
    __half* Vh = (__half*)(smem + 139264);
    __half* Ph = (__half*)(smem + 157696);           // [128][136]

    const int h = blockIdx.x;          // head fastest -> x rows shared in L2
    const int w = blockIdx.y;
    const int tid  = threadIdx.x;
    const int warp = tid >> 5, lane = tid & 31;
    const int b = w >> 5, j = w & 31;

    const size_t abase = (size_t)b * SLEN * DMODEL;

    // ================= Phase 1: QKV GEMM =================
    {
        const int wr = warp >> 2, wc = warp & 3;     // 4x4 grid, 32x48 tiles
        CF acc[2][3];
#pragma unroll
        for (int i = 0; i < 2; i++)
#pragma unroll
            for (int jj = 0; jj < 3; jj++) wmma::fill_fragment(acc[i][jj], 0.0f);

        auto load_chunk = [&](int c, int st) {
            const uint32_t sbase = sb0 + st * FSTG;
            const size_t g = (size_t)c * 64;
#pragma unroll
            for (int q = 0; q < 2; q++) {            // A: 128 rows x 8 c16
                int idx = tid + q * 512;
                int row = idx >> 3, c16 = idx & 7;
                int sp = (j * WIN + row + SHIFT) & (SLEN - 1);   // roll(-shift)
                size_t ar = abase + (size_t)sp * DMODEL + g + c16 * 8;
                CP_ASYNC16(sbase + (uint32_t)(row * 144 + c16 * 16), g_x_hi + ar);
            }
#pragma unroll
            for (int q = 0; q < 3; q++) {            // B: 192 rows x 8 c16
                int idx = tid + q * 512;
                int row = idx >> 3, c16 = idx & 7;
                int grp = row >> 6, r64 = row & 63;
                size_t br = (size_t)(grp * 512 + h * 64 + r64) * DMODEL + g + c16 * 8;
                CP_ASYNC16(sbase + 18432 + (uint32_t)(row * 144 + c16 * 16), g_win_hi + br);
            }
            CP_COMMIT();
        };

        load_chunk(0, 0);
        for (int c = 0; c < 8; c++) {
            if (c < 7) { load_chunk(c + 1, (c + 1) & 1); CP_WAIT(1); }
            else       { CP_WAIT(0); }
            __syncthreads();

            const __half* Ah = (const __half*)(smem + (c & 1) * FSTG);
            const __half* Bh = Ah + 9216;
#pragma unroll
            for (int ks = 0; ks < 4; ks++) {
                HA ah[2];
#pragma unroll
                for (int i = 0; i < 2; i++)
                    wmma::load_matrix_sync(ah[i], Ah + (wr * 32 + i * 16) * 72 + ks * 16, 72);
#pragma unroll
                for (int jj = 0; jj < 3; jj++) {
                    HBc bh;
                    wmma::load_matrix_sync(bh, Bh + (wc * 48 + jj * 16) * 72 + ks * 16, 72);
#pragma unroll
                    for (int i = 0; i < 2; i++)
                        wmma::mma_sync(acc[i][jj], ah[i], bh, acc[i][jj]);
                }
            }
            __syncthreads();
        }

        // stage acc -> Cs (stages dead now)
#pragma unroll
        for (int i = 0; i < 2; i++)
#pragma unroll
            for (int jj = 0; jj < 3; jj++)
                wmma::store_matrix_sync(Cs + (wr * 32 + i * 16) * 200 + wc * 48 + jj * 16,
                                        acc[i][jj], 200, wmma::mem_row_major);
        __syncthreads();

        // bias + (Q scale) + fp16 -> Qh/Kh/Vh.  128 rows x 48 float4-groups.
#pragma unroll
        for (int it = 0; it < 12; it++) {
            int idx = tid + it * 512;
            int r = idx / 48, cg = idx % 48;
            int c4 = cg * 4;
            int grp = c4 >> 6, d = c4 & 63;
            const float* bi = b_in + grp * 512 + h * 64 + d;
            float s = (grp == 0) ? 0.125f : 1.0f;    // exact power-of-2 on Q
            float4 v;
            v.x = (Cs[r * 200 + c4 + 0] + bi[0]) * s;
            v.y = (Cs[r * 200 + c4 + 1] + bi[1]) * s;
            v.z = (Cs[r * 200 + c4 + 2] + bi[2]) * s;
            v.w = (Cs[r * 200 + c4 + 3] + bi[3]) * s;
            __half* dst = (grp == 0 ? Qh : grp == 1 ? Kh : Vh) + r * 72 + d;
            hi_store4(v, dst);
        }
    }
    __syncthreads();

    // ================= Phase 2: S = Q K^T (scale pre-applied) =================
    {
        const int wrS = warp >> 2, wcS = warp & 3;   // 4x4 grid, 32x32 tiles
        CF sacc[2][2];
#pragma unroll
        for (int i = 0; i < 2; i++)
#pragma unroll
            for (int jj = 0; jj < 2; jj++) wmma::fill_fragment(sacc[i][jj], 0.0f);
#pragma unroll
        for (int kk = 0; kk < 4; kk++) {
            HA qh2[2];
#pragma unroll
            for (int i = 0; i < 2; i++)
                wmma::load_matrix_sync(qh2[i], Qh + (wrS * 32 + i * 16) * 72 + kk * 16, 72);
#pragma unroll
            for (int jj = 0; jj < 2; jj++) {
                HBc kh2;
                wmma::load_matrix_sync(kh2, Kh + (wcS * 32 + jj * 16) * 72 + kk * 16, 72);
#pragma unroll
                for (int i = 0; i < 2; i++)
                    wmma::mma_sync(sacc[i][jj], qh2[i], kh2, sacc[i][jj]);
            }
        }
        // Ps overlays region0 (Cs dead); disjoint from Qh/Kh. No pre-sync needed.
#pragma unroll
        for (int i = 0; i < 2; i++)
#pragma unroll
            for (int jj = 0; jj < 2; jj++)
                wmma::store_matrix_sync(Ps + (wrS * 32 + i * 16) * 132 + wcS * 32 + jj * 16,
                                        sacc[i][jj], 132, wmma::mem_row_major);
    }
    __syncthreads();

    // ================= Phase 3: softmax -> fp16 Ph =================
#pragma unroll
    for (int rr = 0; rr < 8; rr++) {
        const int row = warp * 8 + rr;
        const float* prow = Ps + row * 132;
        float v0 = prow[lane], v1 = prow[lane + 32], v2 = prow[lane + 64], v3 = prow[lane + 96];
        float m = fmaxf(fmaxf(v0, v1), fmaxf(v2, v3));
#pragma unroll
        for (int o = 16; o; o >>= 1) m = fmaxf(m, __shfl_xor_sync(0xffffffffu, m, o));
        v0 = __expf(v0 - m); v1 = __expf(v1 - m); v2 = __expf(v2 - m); v3 = __expf(v3 - m);
        float s = v0 + v1 + v2 + v3;
#pragma unroll
        for (int o = 16; o; o >>= 1) s += __shfl_xor_sync(0xffffffffu, s, o);
        float inv = 1.0f / s;
        __half* ph = Ph + row * 136;
        ph[lane]      = __float2half_rn(v0 * inv);
        ph[lane + 32] = __float2half_rn(v1 * inv);
        ph[lane + 64] = __float2half_rn(v2 * inv);
        ph[lane + 96] = __float2half_rn(v3 * inv);
    }
    __syncthreads();

    // ================= Phase 4: O = P V -> g_o_hi =================
    {
        const int wrP = warp >> 1, wcP = warp & 1;   // 8x2 grid, 16x32 tiles
        CF oacc[2];
        wmma::fill_fragment(oacc[0], 0.0f);
        wmma::fill_fragment(oacc[1], 0.0f);
#pragma unroll
        for (int kk = 0; kk < 8; kk++) {
            HA ph2;
            wmma::load_matrix_sync(ph2, Ph + (wrP * 16) * 136 + kk * 16, 136);
#pragma unroll
            for (int jj = 0; jj < 2; jj++) {
                HBr vh2;
                wmma::load_matrix_sync(vh2, Vh + (kk * 16) * 72 + wcP * 32 + jj * 16, 72);
                wmma::mma_sync(oacc[jj], ph2, vh2, oacc[jj]);
            }
        }
        __syncthreads();   // Ps region dead before Os overlay
#pragma unroll
        for (int jj = 0; jj < 2; jj++)
            wmma::store_matrix_sync(Os + (wrP * 16) * 68 + wcP * 32 + jj * 16,
                                    oacc[jj], 68, wmma::mem_row_major);
    }
    __syncthreads();

#pragma unroll
    for (int it = 0; it < 4; it++) {
        int idx = tid + it * 512;          // 128 rows x 16 col-groups
        int r = idx >> 4, cc = (idx & 15) * 4;
        float4 v;
        v.x = Os[r * 68 + cc + 0];
        v.y = Os[r * 68 + cc + 1];
        v.z = Os[r * 68 + cc + 2];
        v.w = Os[r * 68 + cc + 3];
        size_t o = ((size_t)w * WIN + r) * DMODEL + h * HD + cc;
        hi_store4(v, g_o_hi + o);
    }
}

// ---------------------------------------------------------------------------
// Output projection (round-7 config): C[128x256] per CTA = g_o_hi @ w_out^T,
// cp.async 3-stage, 512 threads, warp grid 4x4, warp tile 32x64.
// ---------------------------------------------------------------------------
#define STG_BYTES 55296
#define PROJ_SMEM (3 * STG_BYTES)

__global__ __launch_bounds__(512, 1) void k_proj_out(const float* __restrict__ bias,
                                                     float* __restrict__ outp) {
    extern __shared__ char smem[];
    const uint32_t sb0 = smem_to_u32(smem);
    float* Cs = (float*)smem;              // [128][264]

    const int tid  = threadIdx.x;
    const int warp = tid >> 5;
    const int wr = warp >> 2, wc = warp & 3;
    const int n0 = blockIdx.x * 256;
    const int w  = blockIdx.y;
    const int b  = w >> 5, j = w & 31;

    const size_t abase = (size_t)w * WIN * DMODEL;

    CF acc[2][4];
#pragma unroll
    for (int i = 0; i < 2; i++)
#pragma unroll
        for (int jj = 0; jj < 4; jj++) wmma::fill_fragment(acc[i][jj], 0.0f);

    auto load_chunk = [&](int c, int st) {
        const uint32_t sbase = sb0 + st * STG_BYTES;
        const size_t g = (size_t)c * 64;
#pragma unroll
        for (int q = 0; q < 2; q++) {          // A: 128 rows x 8 c16
            int idx = tid + q * 512;
            int row = idx >> 3, c16 = idx & 7;
            size_t ar = abase + (size_t)row * DMODEL + g + c16 * 8;
            CP_ASYNC16(sbase + (uint32_t)(row * 144 + c16 * 16), g_o_hi + ar);
        }
#pragma unroll
        for (int q = 0; q < 4; q++) {          // B: 256 rows x 8 c16
            int idx = tid + q * 512;
            int row = idx >> 3, c16 = idx & 7;
            size_t br = (size_t)(n0 + row) * DMODEL + g + c16 * 8;
            CP_ASYNC16(sbase + 18432 + (uint32_t)(row * 144 + c16 * 16), g_wout_hi + br);
        }
        CP_COMMIT();
    };

    load_chunk(0, 0);
    load_chunk(1, 1);

    for (int c = 0; c < 8; c++) {
        if (c < 7) CP_WAIT(1); else CP_WAIT(0);
        __syncthreads();
        if (c + 2 < 8) load_chunk(c + 2, (c + 2) % 3);

        const __half* Ah = (const __half*)(smem + (c % 3) * STG_BYTES);
        const __half* Bh = Ah + 9216;
#pragma unroll
        for (int ks = 0; ks < 4; ks++) {
            HA ah[2];
#pragma unroll
            for (int i = 0; i < 2; i++)
                wmma::load_matrix_sync(ah[i], Ah + (wr * 32 + i * 16) * 72 + ks * 16, 72);
#pragma unroll
            for (int jj = 0; jj < 4; jj++) {
                HBc bh;
                wmma::load_matrix_sync(bh, Bh + (wc * 64 + jj * 16) * 72 + ks * 16, 72);
#pragma unroll
                for (int i = 0; i < 2; i++)
                    wmma::mma_sync(acc[i][jj], ah[i], bh, acc[i][jj]);
            }
        }
    }
    __syncthreads();

#pragma unroll
    for (int i = 0; i < 2; i++)
#pragma unroll
        for (int jj = 0; jj < 4; jj++)
            wmma::store_matrix_sync(Cs + (wr * 32 + i * 16) * 264 + wc * 64 + jj * 16,
                                    acc[i][jj], 264, wmma::mem_row_major);
    __syncthreads();

#pragma unroll
    for (int it = 0; it < 16; it++) {
        int idx = tid + it * 512;
        int r = idx >> 6, cc = (idx & 63) * 4;
        float4 v;
        v.x = Cs[r * 264 + cc + 0] + bias[n0 + cc + 0];
        v.y = Cs[r * 264 + cc + 1] + bias[n0 + cc + 1];
        v.z = Cs[r * 264 + cc + 2] + bias[n0 + cc + 2];
        v.w = Cs[r * 264 + cc + 3] + bias[n0 + cc + 3];
        int sp = (j * WIN + r + SHIFT) & (SLEN - 1);   // roll(+shift) scatter
        *(float4*)(outp + ((size_t)b * SLEN + sp) * DMODEL + n0 + cc) = v;
    }
}

// ---------------------------------------------------------------------------
extern "C" void kernel_launch(void* const* d_in, const int* in_sizes, int n_in,
                              void* d_out, int out_size) {
    const float* x     = (const float*)d_in[0];
    const float* w_in  = (const float*)d_in[1];
    const float* b_in  = (const float*)d_in[2];
    const float* w_out = (const float*)d_in[3];
    const float* b_out = (const float*)d_in[4];
    float* out = (float*)d_out;

    cudaFuncSetAttribute(k_fused,    cudaFuncAttributeMaxDynamicSharedMemorySize, FUSED_SMEM);
    cudaFuncSetAttribute(k_proj_out, cudaFuncAttributeMaxDynamicSharedMemorySize, PROJ_SMEM);

    const int n4x  = BATCH * SLEN * DMODEL / 4;     // 16,777,216
    const int n4wi = 3 * DMODEL * DMODEL / 4;       // 196,608
    const int n4wo = DMODEL * DMODEL / 4;           // 65,536
    k_split<<<n4x / 256, 256>>>((const float4*)x, 0, n4x);
    k_split<<<n4wi / 256, 256>>>((const float4*)w_in, 1, n4wi);
    k_split<<<n4wo / 256, 256>>>((const float4*)w_out, 2, n4wo);

    k_fused<<<dim3(NHEADS, NWIN), 512, FUSED_SMEM>>>(b_in);
    k_proj_out<<<dim3(2, NWIN), 512, PROJ_SMEM>>>(b_out, out);
}

// round 11
// speedup vs baseline: 1.0465x; 1.0465x over previous
#include <cuda_runtime.h>
#include <cuda_fp16.h>
#include <mma.h>
#include <cstdint>
using namespace nvcuda;

// Problem constants (fixed by setup_inputs)
#define BATCH   32
#define SLEN    4096
#define DMODEL  512
#define NHEADS  8
#define HD      64
#define WIN     128
#define SHIFT   64
#define NWIN    1024          // total windows (BATCH * 32)

// ---------------------------------------------------------------------------
// Persistent fp16 arrays — all hi-only (calibrated rel_err ~7.0e-4).
// ---------------------------------------------------------------------------
__device__ __align__(16) __half g_x_hi[(size_t)BATCH * SLEN * DMODEL];
__device__ __align__(16) __half g_win_hi[3 * DMODEL * DMODEL];
__device__ __align__(16) __half g_wout_hi[DMODEL * DMODEL];
__device__ __align__(16) __half g_qkv_hi[(size_t)3 * NWIN * NHEADS * WIN * HD];
__device__ __align__(16) __half g_o_hi[(size_t)NWIN * WIN * DMODEL];

// ---------------------------------------------------------------------------
// wmma fp16 types
// ---------------------------------------------------------------------------
using HA  = wmma::fragment<wmma::matrix_a, 16, 16, 16, __half, wmma::row_major>;
using HBc = wmma::fragment<wmma::matrix_b, 16, 16, 16, __half, wmma::col_major>;
using HBr = wmma::fragment<wmma::matrix_b, 16, 16, 16, __half, wmma::row_major>;
using CF  = wmma::fragment<wmma::accumulator, 16, 16, 16, float>;

__device__ __forceinline__ void hi_store4(const float4 v, __half* hi) {
    *reinterpret_cast<__half2*>(hi)     = __halves2half2(__float2half_rn(v.x), __float2half_rn(v.y));
    *reinterpret_cast<__half2*>(hi + 2) = __halves2half2(__float2half_rn(v.z), __float2half_rn(v.w));
}

// ---------------------------------------------------------------------------
// cp.async helpers
// ---------------------------------------------------------------------------
__device__ __forceinline__ uint32_t smem_to_u32(const void* p) {
    uint32_t a;
    asm("{ .reg .u64 t; cvta.to.shared.u64 t, %1; cvt.u32.u64 %0, t; }" : "=r"(a) : "l"(p));
    return a;
}
#define CP_ASYNC16(su32, gptr) \
    asm volatile("cp.async.cg.shared.global [%0], [%1], 16;" :: "r"(su32), "l"(gptr) : "memory")
#define CP_COMMIT() asm volatile("cp.async.commit_group;" ::: "memory")
#define CP_WAIT(n)  asm volatile("cp.async.wait_group %0;" :: "n"(n) : "memory")

// ---------------------------------------------------------------------------
// Prep splits. which: 0 = x, 1 = w_in, 2 = w_out — all hi-only.
// ---------------------------------------------------------------------------
__global__ void k_split(const float4* __restrict__ src, int which, int n4) {
    int i = blockIdx.x * blockDim.x + threadIdx.x;
    if (i >= n4) return;
    float4 v = src[i];
    if (which == 0)      hi_store4(v, g_x_hi + (size_t)i * 4);
    else if (which == 1) hi_store4(v, g_win_hi + (size_t)i * 4);
    else                 hi_store4(v, g_wout_hi + (size_t)i * 4);
}

// ---------------------------------------------------------------------------
// Projection GEMM (R7/R9 config — crossbar-balanced equilibrium, known best):
// C[128x256] per CTA = Ah@Bh^T, cp.async 3-stage, 512 threads, warp grid 4x4,
// warp tile 32x64.
// MODE 0: A = rolled x, B = w_in -> g_qkv_hi, +b_in
// MODE 1: A = g_o_hi,  B = w_out -> fp32 out with roll(+shift), +b_out
// smem per stage: Ah[128][72] (18432 B) + Bh[256][72] (36864 B) = 55296 B.
// 3 stages = 165888 B. Cs fp32 [128][264] (135168 B) overlays.
// ---------------------------------------------------------------------------
#define STG_BYTES 55296
#define PROJ_SMEM (3 * STG_BYTES)

template <int MODE>
__global__ __launch_bounds__(512, 1) void k_proj(const float* __restrict__ bias,
                                                 float* __restrict__ outp) {
    extern __shared__ char smem[];
    const uint32_t sb0 = smem_to_u32(smem);
    float* Cs = (float*)smem;              // [128][264]

    const int tid  = threadIdx.x;
    const int warp = tid >> 5;
    const int wr = warp >> 2, wc = warp & 3;   // 4x4 warp grid, 32x64 warp tiles
    const int n0 = blockIdx.x * 256;
    const int w  = blockIdx.y;
    const int b  = w >> 5, j = w & 31;

    const __half* Asrc_h = (MODE == 0) ? g_x_hi : g_o_hi;
    const __half* Bsrc_h = (MODE == 0) ? g_win_hi : g_wout_hi;

    const size_t abase = (MODE == 0) ? ((size_t)b * SLEN) * DMODEL
                                     : ((size_t)w * WIN) * DMODEL;

    CF acc[2][4];
#pragma unroll
    for (int i = 0; i < 2; i++)
#pragma unroll
        for (int jj = 0; jj < 4; jj++) wmma::fill_fragment(acc[i][jj], 0.0f);

    // ---- async load of one chunk (64 halves of K) into stage `st` ----
    auto load_chunk = [&](int c, int st) {
        const uint32_t sbase = sb0 + st * STG_BYTES;
        const size_t g = (size_t)c * 64;
#pragma unroll
        for (int q = 0; q < 2; q++) {          // A: 128 rows x 8 c16 = 1024
            int idx = tid + q * 512;
            int row = idx >> 3, c16 = idx & 7;
            size_t ar;
            if (MODE == 0) {
                int sp = (j * WIN + row + SHIFT) & (SLEN - 1);   // roll(-shift)
                ar = abase + (size_t)sp * DMODEL + g + c16 * 8;
            } else {
                ar = abase + (size_t)row * DMODEL + g + c16 * 8;
            }
            CP_ASYNC16(sbase + (uint32_t)(row * 144 + c16 * 16), Asrc_h + ar);
        }
#pragma unroll
        for (int q = 0; q < 4; q++) {          // B: 256 rows x 8 c16 = 2048
            int idx = tid + q * 512;
            int row = idx >> 3, c16 = idx & 7;
            size_t br = (size_t)(n0 + row) * DMODEL + g + c16 * 8;
            CP_ASYNC16(sbase + 18432 + (uint32_t)(row * 144 + c16 * 16), Bsrc_h + br);
        }
        CP_COMMIT();
    };

    load_chunk(0, 0);                          // prologue: 2 chunks in flight
    load_chunk(1, 1);

    for (int c = 0; c < 8; c++) {
        if (c < 7) CP_WAIT(1); else CP_WAIT(0);   // chunk c landed
        __syncthreads();                          // stage (c+2)%3 is free
        if (c + 2 < 8) load_chunk(c + 2, (c + 2) % 3);

        const __half* Ah = (const __half*)(smem + (c % 3) * STG_BYTES);
        const __half* Bh = Ah + 9216;
#pragma unroll
        for (int ks = 0; ks < 4; ks++) {
            HA ah[2];
#pragma unroll
            for (int i = 0; i < 2; i++)
                wmma::load_matrix_sync(ah[i], Ah + (wr * 32 + i * 16) * 72 + ks * 16, 72);
#pragma unroll
            for (int jj = 0; jj < 4; jj++) {
                HBc bh;
                wmma::load_matrix_sync(bh, Bh + (wc * 64 + jj * 16) * 72 + ks * 16, 72);
#pragma unroll
                for (int i = 0; i < 2; i++)
                    wmma::mma_sync(acc[i][jj], ah[i], bh, acc[i][jj]);
            }
        }
    }
    __syncthreads();     // all MMA reads done before Cs overlays stages

#pragma unroll
    for (int i = 0; i < 2; i++)
#pragma unroll
        for (int jj = 0; jj < 4; jj++)
            wmma::store_matrix_sync(Cs + (wr * 32 + i * 16) * 264 + wc * 64 + jj * 16,
                                    acc[i][jj], 264, wmma::mem_row_major);
    __syncthreads();

#pragma unroll
    for (int it = 0; it < 16; it++) {
        int idx = tid + it * 512;              // 128 rows x 64 col-groups
        int r = idx >> 6, cc = (idx & 63) * 4;
        float4 v;
        v.x = Cs[r * 264 + cc + 0] + bias[n0 + cc + 0];
        v.y = Cs[r * 264 + cc + 1] + bias[n0 + cc + 1];
        v.z = Cs[r * 264 + cc + 2] + bias[n0 + cc + 2];
        v.w = Cs[r * 264 + cc + 3] + bias[n0 + cc + 3];
        if (MODE == 0) {
            int gc = n0 + cc;
            int p = gc >> 9, hh = (gc >> 6) & 7, d = gc & 63;
            size_t o = ((((size_t)p * NWIN + w) * NHEADS + hh) * WIN + r) * HD + d;
            hi_store4(v, g_qkv_hi + o);
        } else {
            int sp = (j * WIN + r + SHIFT) & (SLEN - 1);   // roll(+shift) scatter
            *(float4*)(outp + ((size_t)b * SLEN + sp) * DMODEL + n0 + cc) = v;
        }
    }
}

// ---------------------------------------------------------------------------
// Attention (hi-only): one CTA per (row-half, head, window). 256 threads,
// 2 CTAs/SM. 64 query rows vs full 128-key window.
// Grid = (2, NHEADS, NWIN) with hf FASTEST so the two CTAs sharing a
// (window, head) — which both read the full K and V tiles — are co-scheduled
// and the second read hits L2.
// smem (half offsets):
//   [0, 16896)     Qh [64][72] at 0; Ps fp32 [64][132] overlay; Os fp32
//                  [64][68] overlay
//   [16896, 26112) Kh [128][72]
//   [26112, 35328) Vh [128][72]
//   [35328, 44032) Ph [64][136]
// total 44032 halves = 88064 B -> 2 CTAs/SM.
// ---------------------------------------------------------------------------
#define ATTN_SMEM 88064

__global__ __launch_bounds__(256, 2) void k_attn() {
    extern __shared__ __half smh[];
    __half* Qh = smh;                    // [64][72]
    float*  Ps = (float*)smh;            // [64][132]
    __half* Kh = smh + 16896;            // [128][72]
    __half* Vh = smh + 26112;            // [128][72]
    __half* Ph = smh + 35328;            // [64][136]
    float*  Os = (float*)smh;            // [64][68]

    const int hf = blockIdx.x, h = blockIdx.y, w = blockIdx.z;
    const int tid = threadIdx.x;
    const int warp = tid >> 5, lane = tid & 31;

    const size_t part = (size_t)NWIN * NHEADS * WIN * HD;
    const size_t bq = ((size_t)w * NHEADS + h) * (WIN * HD);

    {   // Q (this CTA's 64 rows): 4 threads/row; K,V (128 rows): 2 iters
        const int r = tid >> 2, cg = (tid & 3) * 16;
        const size_t so = bq + (size_t)(hf * 64 + r) * HD + cg;
        const int dst = r * 72 + cg;
        *(uint4*)&Qh[dst]     = *(const uint4*)(g_qkv_hi + so);
        *(uint4*)&Qh[dst + 8] = *(const uint4*)(g_qkv_hi + so + 8);
#pragma unroll
        for (int q = 0; q < 2; q++) {
            int idx = tid + q * 256;
            int kr = idx >> 2, kcg = (idx & 3) * 16;
            size_t ko = bq + (size_t)kr * HD + kcg;
            int kdst = kr * 72 + kcg;
            *(uint4*)&Kh[kdst]     = *(const uint4*)(g_qkv_hi + part + ko);
            *(uint4*)&Kh[kdst + 8] = *(const uint4*)(g_qkv_hi + part + ko + 8);
            *(uint4*)&Vh[kdst]     = *(const uint4*)(g_qkv_hi + 2 * part + ko);
            *(uint4*)&Vh[kdst + 8] = *(const uint4*)(g_qkv_hi + 2 * part + ko + 8);
        }
    }
    __syncthreads();

    // ---- S = Q K^T / 8 : 8 warps, 2x4 grid, 32x32 tiles ----
    {
        const int wrS = warp >> 2, wcS = warp & 3;
        CF sacc[2][2];
#pragma unroll
        for (int i = 0; i < 2; i++)
#pragma unroll
            for (int jj = 0; jj < 2; jj++) wmma::fill_fragment(sacc[i][jj], 0.0f);
#pragma unroll
        for (int kk = 0; kk < 4; kk++) {
            HA qh2[2];
#pragma unroll
            for (int i = 0; i < 2; i++)
                wmma::load_matrix_sync(qh2[i], Qh + (wrS * 32 + i * 16) * 72 + kk * 16, 72);
#pragma unroll
            for (int jj = 0; jj < 2; jj++) {
                HBc kh2;
                wmma::load_matrix_sync(kh2, Kh + (wcS * 32 + jj * 16) * 72 + kk * 16, 72);
#pragma unroll
                for (int i = 0; i < 2; i++)
                    wmma::mma_sync(sacc[i][jj], qh2[i], kh2, sacc[i][jj]);
            }
        }
        __syncthreads();   // Q reads complete before Ps overlays
#pragma unroll
        for (int i = 0; i < 2; i++)
#pragma unroll
            for (int jj = 0; jj < 2; jj++) {
#pragma unroll
                for (int e = 0; e < sacc[i][jj].num_elements; e++) sacc[i][jj].x[e] *= 0.125f;
                wmma::store_matrix_sync(Ps + (wrS * 32 + i * 16) * 132 + wcS * 32 + jj * 16,
                                        sacc[i][jj], 132, wmma::mem_row_major);
            }
    }
    __syncthreads();

    // ---- softmax: 8 warps x 8 rows, write fp16 P (hi only) ----
#pragma unroll
    for (int rr = 0; rr < 8; rr++) {
        const int row = warp * 8 + rr;
        const float* prow = Ps + row * 132;
        float v0 = prow[lane], v1 = prow[lane + 32], v2 = prow[lane + 64], v3 = prow[lane + 96];
        float m = fmaxf(fmaxf(v0, v1), fmaxf(v2, v3));
#pragma unroll
        for (int o = 16; o; o >>= 1) m = fmaxf(m, __shfl_xor_sync(0xffffffffu, m, o));
        v0 = __expf(v0 - m); v1 = __expf(v1 - m); v2 = __expf(v2 - m); v3 = __expf(v3 - m);
        float s = v0 + v1 + v2 + v3;
#pragma unroll
        for (int o = 16; o; o >>= 1) s += __shfl_xor_sync(0xffffffffu, s, o);
        float inv = 1.0f / s;
        __half* ph = Ph + row * 136;
        ph[lane]      = __float2half_rn(v0 * inv);
        ph[lane + 32] = __float2half_rn(v1 * inv);
        ph[lane + 64] = __float2half_rn(v2 * inv);
        ph[lane + 96] = __float2half_rn(v3 * inv);
    }
    __syncthreads();

    // ---- O = P V : 8 warps, 4x2 grid, 16x32 tiles ----
    {
        const int wrP = warp >> 1, wcP = warp & 1;
        CF oacc[2];
        wmma::fill_fragment(oacc[0], 0.0f);
        wmma::fill_fragment(oacc[1], 0.0f);
#pragma unroll
        for (int kk = 0; kk < 8; kk++) {
            HA ph2;
            wmma::load_matrix_sync(ph2, Ph + (wrP * 16) * 136 + kk * 16, 136);
#pragma unroll
            for (int jj = 0; jj < 2; jj++) {
                HBr vh2;
                wmma::load_matrix_sync(vh2, Vh + (kk * 16) * 72 + wcP * 32 + jj * 16, 72);
                wmma::mma_sync(oacc[jj], ph2, vh2, oacc[jj]);
            }
        }
        __syncthreads();   // Ps region dead before Os overlay
#pragma unroll
        for (int jj = 0; jj < 2; jj++)
            wmma::store_matrix_sync(Os + (wrP * 16) * 68 + wcP * 32 + jj * 16,
                                    oacc[jj], 68, wmma::mem_row_major);
    }
    __syncthreads();

    // ---- store O (hi only) ----
#pragma unroll
    for (int it = 0; it < 4; it++) {
        int idx = tid + it * 256;          // 64 rows x 16 col-groups
        int r = idx >> 4, cc = (idx & 15) * 4;
        float4 v;
        v.x = Os[r * 68 + cc + 0];
        v.y = Os[r * 68 + cc + 1];
        v.z = Os[r * 68 + cc + 2];
        v.w = Os[r * 68 + cc + 3];
        size_t o = ((size_t)w * WIN + hf * 64 + r) * DMODEL + h * HD + cc;
        hi_store4(v, g_o_hi + o);
    }
}

// ---------------------------------------------------------------------------
extern "C" void kernel_launch(void* const* d_in, const int* in_sizes, int n_in,
                              void* d_out, int out_size) {
    const float* x     = (const float*)d_in[0];
    const float* w_in  = (const float*)d_in[1];
    const float* b_in  = (const float*)d_in[2];
    const float* w_out = (const float*)d_in[3];
    const float* b_out = (const float*)d_in[4];
    float* out = (float*)d_out;

    cudaFuncSetAttribute(k_proj<0>, cudaFuncAttributeMaxDynamicSharedMemorySize, PROJ_SMEM);
    cudaFuncSetAttribute(k_proj<1>, cudaFuncAttributeMaxDynamicSharedMemorySize, PROJ_SMEM);
    cudaFuncSetAttribute(k_attn,    cudaFuncAttributeMaxDynamicSharedMemorySize, ATTN_SMEM);

    const int n4x  = BATCH * SLEN * DMODEL / 4;     // 16,777,216
    const int n4wi = 3 * DMODEL * DMODEL / 4;       // 196,608
    const int n4wo = DMODEL * DMODEL / 4;           // 65,536
    k_split<<<n4x / 256, 256>>>((const float4*)x, 0, n4x);
    k_split<<<n4wi / 256, 256>>>((const float4*)w_in, 1, n4wi);
    k_split<<<n4wo / 256, 256>>>((const float4*)w_out, 2, n4wo);

    k_proj<0><<<dim3(6, NWIN), 512, PROJ_SMEM>>>(b_in, nullptr);
    k_attn<<<dim3(2, NHEADS, NWIN), 256, ATTN_SMEM>>>();
    k_proj<1><<<dim3(2, NWIN), 512, PROJ_SMEM>>>(b_out, out);
}

// round 12
// speedup vs baseline: 1.0638x; 1.0166x over previous
#include <cuda_runtime.h>
#include <cuda_fp16.h>
#include <mma.h>
#include <cstdint>
using namespace nvcuda;

// Problem constants (fixed by setup_inputs)
#define BATCH   32
#define SLEN    4096
#define DMODEL  512
#define NHEADS  8
#define HD      64
#define WIN     128
#define SHIFT   64
#define NWIN    1024          // total windows (BATCH * 32)

// ---------------------------------------------------------------------------
// Persistent fp16 arrays — all hi-only (calibrated rel_err ~7.0e-4).
// ---------------------------------------------------------------------------
__device__ __align__(16) __half g_x_hi[(size_t)BATCH * SLEN * DMODEL];
__device__ __align__(16) __half g_win_hi[3 * DMODEL * DMODEL];
__device__ __align__(16) __half g_wout_hi[DMODEL * DMODEL];
__device__ __align__(16) __half g_qkv_hi[(size_t)3 * NWIN * NHEADS * WIN * HD];
__device__ __align__(16) __half g_o_hi[(size_t)NWIN * WIN * DMODEL];

// ---------------------------------------------------------------------------
// wmma fp16 types
// ---------------------------------------------------------------------------
using HA  = wmma::fragment<wmma::matrix_a, 16, 16, 16, __half, wmma::row_major>;
using HBc = wmma::fragment<wmma::matrix_b, 16, 16, 16, __half, wmma::col_major>;
using HBr = wmma::fragment<wmma::matrix_b, 16, 16, 16, __half, wmma::row_major>;
using CF  = wmma::fragment<wmma::accumulator, 16, 16, 16, float>;

__device__ __forceinline__ void hi_store4(const float4 v, __half* hi) {
    *reinterpret_cast<__half2*>(hi)     = __halves2half2(__float2half_rn(v.x), __float2half_rn(v.y));
    *reinterpret_cast<__half2*>(hi + 2) = __halves2half2(__float2half_rn(v.z), __float2half_rn(v.w));
}

// ---------------------------------------------------------------------------
// cp.async helpers
// ---------------------------------------------------------------------------
__device__ __forceinline__ uint32_t smem_to_u32(const void* p) {
    uint32_t a;
    asm("{ .reg .u64 t; cvta.to.shared.u64 t, %1; cvt.u32.u64 %0, t; }" : "=r"(a) : "l"(p));
    return a;
}
#define CP_ASYNC16(su32, gptr) \
    asm volatile("cp.async.cg.shared.global [%0], [%1], 16;" :: "r"(su32), "l"(gptr) : "memory")
#define CP_COMMIT() asm volatile("cp.async.commit_group;" ::: "memory")
#define CP_WAIT(n)  asm volatile("cp.async.wait_group %0;" :: "n"(n) : "memory")

// ---------------------------------------------------------------------------
// Prep splits. which: 0 = x, 1 = w_in, 2 = w_out — all hi-only.
// ---------------------------------------------------------------------------
__global__ void k_split(const float4* __restrict__ src, int which, int n4) {
    int i = blockIdx.x * blockDim.x + threadIdx.x;
    if (i >= n4) return;
    float4 v = src[i];
    if (which == 0)      hi_store4(v, g_x_hi + (size_t)i * 4);
    else if (which == 1) hi_store4(v, g_win_hi + (size_t)i * 4);
    else                 hi_store4(v, g_wout_hi + (size_t)i * 4);
}

// ---------------------------------------------------------------------------
// Projection GEMM (R7/R9 config — crossbar-balanced equilibrium, frozen):
// C[128x256] per CTA = Ah@Bh^T, cp.async 3-stage, 512 threads, warp grid 4x4,
// warp tile 32x64.
// MODE 0: A = rolled x, B = w_in -> g_qkv_hi, +b_in
// MODE 1: A = g_o_hi,  B = w_out -> fp32 out with roll(+shift), +b_out
// ---------------------------------------------------------------------------
#define STG_BYTES 55296
#define PROJ_SMEM (3 * STG_BYTES)

template <int MODE>
__global__ __launch_bounds__(512, 1) void k_proj(const float* __restrict__ bias,
                                                 float* __restrict__ outp) {
    extern __shared__ char smem[];
    const uint32_t sb0 = smem_to_u32(smem);
    float* Cs = (float*)smem;              // [128][264]

    const int tid  = threadIdx.x;
    const int warp = tid >> 5;
    const int wr = warp >> 2, wc = warp & 3;
    const int n0 = blockIdx.x * 256;
    const int w  = blockIdx.y;
    const int b  = w >> 5, j = w & 31;

    const __half* Asrc_h = (MODE == 0) ? g_x_hi : g_o_hi;
    const __half* Bsrc_h = (MODE == 0) ? g_win_hi : g_wout_hi;

    const size_t abase = (MODE == 0) ? ((size_t)b * SLEN) * DMODEL
                                     : ((size_t)w * WIN) * DMODEL;

    CF acc[2][4];
#pragma unroll
    for (int i = 0; i < 2; i++)
#pragma unroll
        for (int jj = 0; jj < 4; jj++) wmma::fill_fragment(acc[i][jj], 0.0f);

    auto load_chunk = [&](int c, int st) {
        const uint32_t sbase = sb0 + st * STG_BYTES;
        const size_t g = (size_t)c * 64;
#pragma unroll
        for (int q = 0; q < 2; q++) {          // A: 128 rows x 8 c16
            int idx = tid + q * 512;
            int row = idx >> 3, c16 = idx & 7;
            size_t ar;
            if (MODE == 0) {
                int sp = (j * WIN + row + SHIFT) & (SLEN - 1);   // roll(-shift)
                ar = abase + (size_t)sp * DMODEL + g + c16 * 8;
            } else {
                ar = abase + (size_t)row * DMODEL + g + c16 * 8;
            }
            CP_ASYNC16(sbase + (uint32_t)(row * 144 + c16 * 16), Asrc_h + ar);
        }
#pragma unroll
        for (int q = 0; q < 4; q++) {          // B: 256 rows x 8 c16
            int idx = tid + q * 512;
            int row = idx >> 3, c16 = idx & 7;
            size_t br = (size_t)(n0 + row) * DMODEL + g + c16 * 8;
            CP_ASYNC16(sbase + 18432 + (uint32_t)(row * 144 + c16 * 16), Bsrc_h + br);
        }
        CP_COMMIT();
    };

    load_chunk(0, 0);
    load_chunk(1, 1);

    for (int c = 0; c < 8; c++) {
        if (c < 7) CP_WAIT(1); else CP_WAIT(0);
        __syncthreads();
        if (c + 2 < 8) load_chunk(c + 2, (c + 2) % 3);

        const __half* Ah = (const __half*)(smem + (c % 3) * STG_BYTES);
        const __half* Bh = Ah + 9216;
#pragma unroll
        for (int ks = 0; ks < 4; ks++) {
            HA ah[2];
#pragma unroll
            for (int i = 0; i < 2; i++)
                wmma::load_matrix_sync(ah[i], Ah + (wr * 32 + i * 16) * 72 + ks * 16, 72);
#pragma unroll
            for (int jj = 0; jj < 4; jj++) {
                HBc bh;
                wmma::load_matrix_sync(bh, Bh + (wc * 64 + jj * 16) * 72 + ks * 16, 72);
#pragma unroll
                for (int i = 0; i < 2; i++)
                    wmma::mma_sync(acc[i][jj], ah[i], bh, acc[i][jj]);
            }
        }
    }
    __syncthreads();

#pragma unroll
    for (int i = 0; i < 2; i++)
#pragma unroll
        for (int jj = 0; jj < 4; jj++)
            wmma::store_matrix_sync(Cs + (wr * 32 + i * 16) * 264 + wc * 64 + jj * 16,
                                    acc[i][jj], 264, wmma::mem_row_major);
    __syncthreads();

#pragma unroll
    for (int it = 0; it < 16; it++) {
        int idx = tid + it * 512;
        int r = idx >> 6, cc = (idx & 63) * 4;
        float4 v;
        v.x = Cs[r * 264 + cc + 0] + bias[n0 + cc + 0];
        v.y = Cs[r * 264 + cc + 1] + bias[n0 + cc + 1];
        v.z = Cs[r * 264 + cc + 2] + bias[n0 + cc + 2];
        v.w = Cs[r * 264 + cc + 3] + bias[n0 + cc + 3];
        if (MODE == 0) {
            int gc = n0 + cc;
            int p = gc >> 9, hh = (gc >> 6) & 7, d = gc & 63;
            size_t o = ((((size_t)p * NWIN + w) * NHEADS + hh) * WIN + r) * HD + d;
            hi_store4(v, g_qkv_hi + o);
        } else {
            int sp = (j * WIN + r + SHIFT) & (SLEN - 1);   // roll(+shift)
            *(float4*)(outp + ((size_t)b * SLEN + sp) * DMODEL + n0 + cc) = v;
        }
    }
}

// ---------------------------------------------------------------------------
// Attention (hi-only, FULL window per CTA, K/V read ONCE): one CTA per
// (head, window), 256 threads, 2 CTAs/SM via row-overlay smem scheme.
//
// smem map:
//   Ps region: 128 rows x 560 B (stride 140 floats) = 71680 B. Tenants:
//     - Qh [128][72] fp16 at byte 0      (dead after S phase)
//     - Kh [128][72] fp16 at byte 18432  (dead after S phase)
//     - Ps fp32 row r: floats [r*140, r*140+128)   (S scores)
//     - Ph fp16 row r: bytes  [r*560, r*560+256)   (written by softmax AFTER
//       that warp has read its own Ps row into registers; row-exclusive)
//     - Os fp32 row r: floats [r*140+72, r*140+140) (disjoint from Ph bytes)
//   Vh [128][72] fp16 at 71680 (preserved until PV done)
// total 90112 B -> 2 CTAs/SM.
//
// Phases: load QKV -> S (4x2 warp grid, 32x64 tiles) -> softmax (8 warps x
// 16 rows) -> PV (8 warps, 16x64 tiles) -> store O.
// Per-element math identical to R11 (same K-order, same scale placement).
// ---------------------------------------------------------------------------
#define ATTN_SMEM 90112

__global__ __launch_bounds__(256, 2) void k_attn() {
    extern __shared__ char sm[];
    __half* Qh = (__half*)sm;                  // [128][72]
    __half* Kh = (__half*)(sm + 18432);        // [128][72]
    float*  Ps = (float*)sm;                   // stride 140 floats
    __half* Ph = (__half*)sm;                  // stride 280 halves, 128 used
    float*  Os = (float*)sm;                   // row r at r*140+72
    __half* Vh = (__half*)(sm + 71680);        // [128][72]

    const int h = blockIdx.x, w = blockIdx.y;
    const int tid = threadIdx.x;
    const int warp = tid >> 5, lane = tid & 31;

    const size_t part = (size_t)NWIN * NHEADS * WIN * HD;
    const size_t bq = ((size_t)w * NHEADS + h) * (WIN * HD);

    {   // loads: 2 threads per row, 32 halves (4 x uint4) each, per array
        const int r = tid >> 1, cg = (tid & 1) * 32;
        const size_t so = bq + (size_t)r * HD + cg;
        const int dst = r * 72 + cg;
#pragma unroll
        for (int q = 0; q < 4; q++) {
            *(uint4*)&Qh[dst + q * 8] = *(const uint4*)(g_qkv_hi + so + q * 8);
            *(uint4*)&Kh[dst + q * 8] = *(const uint4*)(g_qkv_hi + part + so + q * 8);
            *(uint4*)&Vh[dst + q * 8] = *(const uint4*)(g_qkv_hi + 2 * part + so + q * 8);
        }
    }
    __syncthreads();

    // ---- S = Q K^T / 8 : 8 warps, 4x2 grid, 32x64 tiles ----
    {
        const int wrS = warp >> 1, wcS = warp & 1;
        CF sacc[2][4];
#pragma unroll
        for (int i = 0; i < 2; i++)
#pragma unroll
            for (int jj = 0; jj < 4; jj++) wmma::fill_fragment(sacc[i][jj], 0.0f);
#pragma unroll
        for (int kk = 0; kk < 4; kk++) {
            HA qh2[2];
#pragma unroll
            for (int i = 0; i < 2; i++)
                wmma::load_matrix_sync(qh2[i], Qh + (wrS * 32 + i * 16) * 72 + kk * 16, 72);
#pragma unroll
            for (int jj = 0; jj < 4; jj++) {
                HBc kh2;
                wmma::load_matrix_sync(kh2, Kh + (wcS * 64 + jj * 16) * 72 + kk * 16, 72);
#pragma unroll
                for (int i = 0; i < 2; i++)
                    wmma::mma_sync(sacc[i][jj], qh2[i], kh2, sacc[i][jj]);
            }
        }
        __syncthreads();   // ALL warps' Q/K reads done before Ps overlays them
#pragma unroll
        for (int i = 0; i < 2; i++)
#pragma unroll
            for (int jj = 0; jj < 4; jj++) {
#pragma unroll
                for (int e = 0; e < sacc[i][jj].num_elements; e++) sacc[i][jj].x[e] *= 0.125f;
                wmma::store_matrix_sync(Ps + (wrS * 32 + i * 16) * 140 + wcS * 64 + jj * 16,
                                        sacc[i][jj], 140, wmma::mem_row_major);
            }
    }
    __syncthreads();

    // ---- softmax: 8 warps x 16 rows; reads own Ps row into regs, THEN
    //      writes fp16 Ph into the head of the same row (row-exclusive) ----
#pragma unroll
    for (int rr = 0; rr < 16; rr++) {
        const int row = warp * 16 + rr;
        const float* prow = Ps + row * 140;
        float v0 = prow[lane], v1 = prow[lane + 32], v2 = prow[lane + 64], v3 = prow[lane + 96];
        float m = fmaxf(fmaxf(v0, v1), fmaxf(v2, v3));
#pragma unroll
        for (int o = 16; o; o >>= 1) m = fmaxf(m, __shfl_xor_sync(0xffffffffu, m, o));
        v0 = __expf(v0 - m); v1 = __expf(v1 - m); v2 = __expf(v2 - m); v3 = __expf(v3 - m);
        float s = v0 + v1 + v2 + v3;
#pragma unroll
        for (int o = 16; o; o >>= 1) s += __shfl_xor_sync(0xffffffffu, s, o);
        float inv = 1.0f / s;
        __half* ph = Ph + row * 280;
        ph[lane]      = __float2half_rn(v0 * inv);
        ph[lane + 32] = __float2half_rn(v1 * inv);
        ph[lane + 64] = __float2half_rn(v2 * inv);
        ph[lane + 96] = __float2half_rn(v3 * inv);
    }
    __syncthreads();

    // ---- O = P V : 8 warps, one 16x64 tile each ----
    {
        CF oacc[4];
#pragma unroll
        for (int jj = 0; jj < 4; jj++) wmma::fill_fragment(oacc[jj], 0.0f);
#pragma unroll
        for (int kk = 0; kk < 8; kk++) {
            HA ph2;
            wmma::load_matrix_sync(ph2, Ph + (warp * 16) * 280 + kk * 16, 280);
#pragma unroll
            for (int jj = 0; jj < 4; jj++) {
                HBr vh2;
                wmma::load_matrix_sync(vh2, Vh + (kk * 16) * 72 + jj * 16, 72);
                wmma::mma_sync(oacc[jj], ph2, vh2, oacc[jj]);
            }
        }
        // Os bytes [288,560) per row are disjoint from Ph bytes [0,256);
        // Vh untouched. Still sync for rigor before cross-region stores.
        __syncthreads();
#pragma unroll
        for (int jj = 0; jj < 4; jj++)
            wmma::store_matrix_sync(Os + (warp * 16) * 140 + 72 + jj * 16,
                                    oacc[jj], 140, wmma::mem_row_major);
    }
    __syncthreads();

    // ---- store O (hi only) ----
#pragma unroll
    for (int it = 0; it < 8; it++) {
        int idx = tid + it * 256;          // 128 rows x 16 col-groups
        int r = idx >> 4, cc = (idx & 15) * 4;
        float4 v;
        v.x = Os[r * 140 + 72 + cc + 0];
        v.y = Os[r * 140 + 72 + cc + 1];
        v.z = Os[r * 140 + 72 + cc + 2];
        v.w = Os[r * 140 + 72 + cc + 3];
        size_t o = ((size_t)w * WIN + r) * DMODEL + h * HD + cc;
        hi_store4(v, g_o_hi + o);
    }
}

// ---------------------------------------------------------------------------
extern "C" void kernel_launch(void* const* d_in, const int* in_sizes, int n_in,
                              void* d_out, int out_size) {
    const float* x     = (const float*)d_in[0];
    const float* w_in  = (const float*)d_in[1];
    const float* b_in  = (const float*)d_in[2];
    const float* w_out = (const float*)d_in[3];
    const float* b_out = (const float*)d_in[4];
    float* out = (float*)d_out;

    cudaFuncSetAttribute(k_proj<0>, cudaFuncAttributeMaxDynamicSharedMemorySize, PROJ_SMEM);
    cudaFuncSetAttribute(k_proj<1>, cudaFuncAttributeMaxDynamicSharedMemorySize, PROJ_SMEM);
    cudaFuncSetAttribute(k_attn,    cudaFuncAttributeMaxDynamicSharedMemorySize, ATTN_SMEM);

    const int n4x  = BATCH * SLEN * DMODEL / 4;     // 16,777,216
    const int n4wi = 3 * DMODEL * DMODEL / 4;       // 196,608
    const int n4wo = DMODEL * DMODEL / 4;           // 65,536
    k_split<<<n4x / 256, 256>>>((const float4*)x, 0, n4x);
    k_split<<<n4wi / 256, 256>>>((const float4*)w_in, 1, n4wi);
    k_split<<<n4wo / 256, 256>>>((const float4*)w_out, 2, n4wo);

    k_proj<0><<<dim3(6, NWIN), 512, PROJ_SMEM>>>(b_in, nullptr);
    k_attn<<<dim3(NHEADS, NWIN), 256, ATTN_SMEM>>>();
    k_proj<1><<<dim3(2, NWIN), 512, PROJ_SMEM>>>(b_out, out);
}

// round 13
// speedup vs baseline: 1.0752x; 1.0107x over previous
#include <cuda_runtime.h>
#include <cuda_fp16.h>
#include <mma.h>
#include <cstdint>
using namespace nvcuda;

// Problem constants (fixed by setup_inputs)
#define BATCH   32
#define SLEN    4096
#define DMODEL  512
#define NHEADS  8
#define HD      64
#define WIN     128
#define SHIFT   64
#define NWIN    1024          // total windows (BATCH * 32)

// ---------------------------------------------------------------------------
// Persistent fp16 arrays — all hi-only (calibrated rel_err ~7.0e-4).
// ---------------------------------------------------------------------------
__device__ __align__(16) __half g_x_hi[(size_t)BATCH * SLEN * DMODEL];
__device__ __align__(16) __half g_win_hi[3 * DMODEL * DMODEL];
__device__ __align__(16) __half g_wout_hi[DMODEL * DMODEL];
__device__ __align__(16) __half g_qkv_hi[(size_t)3 * NWIN * NHEADS * WIN * HD];
__device__ __align__(16) __half g_o_hi[(size_t)NWIN * WIN * DMODEL];

// ---------------------------------------------------------------------------
// wmma fp16 types
// ---------------------------------------------------------------------------
using HA  = wmma::fragment<wmma::matrix_a, 16, 16, 16, __half, wmma::row_major>;
using HBc = wmma::fragment<wmma::matrix_b, 16, 16, 16, __half, wmma::col_major>;
using HBr = wmma::fragment<wmma::matrix_b, 16, 16, 16, __half, wmma::row_major>;
using CF  = wmma::fragment<wmma::accumulator, 16, 16, 16, float>;

__device__ __forceinline__ void hi_store4(const float4 v, __half* hi) {
    *reinterpret_cast<__half2*>(hi)     = __halves2half2(__float2half_rn(v.x), __float2half_rn(v.y));
    *reinterpret_cast<__half2*>(hi + 2) = __halves2half2(__float2half_rn(v.z), __float2half_rn(v.w));
}

// ---------------------------------------------------------------------------
// cp.async helpers
// ---------------------------------------------------------------------------
__device__ __forceinline__ uint32_t smem_to_u32(const void* p) {
    uint32_t a;
    asm("{ .reg .u64 t; cvta.to.shared.u64 t, %1; cvt.u32.u64 %0, t; }" : "=r"(a) : "l"(p));
    return a;
}
#define CP_ASYNC16(su32, gptr) \
    asm volatile("cp.async.cg.shared.global [%0], [%1], 16;" :: "r"(su32), "l"(gptr) : "memory")
#define CP_COMMIT() asm volatile("cp.async.commit_group;" ::: "memory")
#define CP_WAIT(n)  asm volatile("cp.async.wait_group %0;" :: "n"(n) : "memory")

// ---------------------------------------------------------------------------
// Prep splits, single merged launch over x ++ w_in ++ w_out (all hi-only).
// ---------------------------------------------------------------------------
#define N4X  (BATCH * SLEN * DMODEL / 4)        // 16,777,216
#define N4WI (3 * DMODEL * DMODEL / 4)          // 196,608
#define N4WO (DMODEL * DMODEL / 4)              // 65,536
#define N4ALL (N4X + N4WI + N4WO)

__global__ void k_split_all(const float4* __restrict__ x,
                            const float4* __restrict__ w_in,
                            const float4* __restrict__ w_out) {
    int i = blockIdx.x * blockDim.x + threadIdx.x;
    if (i >= N4ALL) return;
    if (i < N4X) {
        hi_store4(x[i], g_x_hi + (size_t)i * 4);
    } else if (i < N4X + N4WI) {
        int k = i - N4X;
        hi_store4(w_in[k], g_win_hi + (size_t)k * 4);
    } else {
        int k = i - N4X - N4WI;
        hi_store4(w_out[k], g_wout_hi + (size_t)k * 4);
    }
}

// ---------------------------------------------------------------------------
// Projection GEMM (R7/R9 config — crossbar-balanced equilibrium, frozen):
// C[128x256] per CTA = Ah@Bh^T, cp.async 3-stage, 512 threads, warp grid 4x4,
// warp tile 32x64.
// MODE 0: A = rolled x, B = w_in -> g_qkv_hi, +b_in
// MODE 1: A = g_o_hi,  B = w_out -> fp32 out with roll(+shift), +b_out
// ---------------------------------------------------------------------------
#define STG_BYTES 55296
#define PROJ_SMEM (3 * STG_BYTES)

template <int MODE>
__global__ __launch_bounds__(512, 1) void k_proj(const float* __restrict__ bias,
                                                 float* __restrict__ outp) {
    extern __shared__ char smem[];
    const uint32_t sb0 = smem_to_u32(smem);
    float* Cs = (float*)smem;              // [128][264]

    const int tid  = threadIdx.x;
    const int warp = tid >> 5;
    const int wr = warp >> 2, wc = warp & 3;
    const int n0 = blockIdx.x * 256;
    const int w  = blockIdx.y;
    const int b  = w >> 5, j = w & 31;

    const __half* Asrc_h = (MODE == 0) ? g_x_hi : g_o_hi;
    const __half* Bsrc_h = (MODE == 0) ? g_win_hi : g_wout_hi;

    const size_t abase = (MODE == 0) ? ((size_t)b * SLEN) * DMODEL
                                     : ((size_t)w * WIN) * DMODEL;

    CF acc[2][4];
#pragma unroll
    for (int i = 0; i < 2; i++)
#pragma unroll
        for (int jj = 0; jj < 4; jj++) wmma::fill_fragment(acc[i][jj], 0.0f);

    auto load_chunk = [&](int c, int st) {
        const uint32_t sbase = sb0 + st * STG_BYTES;
        const size_t g = (size_t)c * 64;
#pragma unroll
        for (int q = 0; q < 2; q++) {          // A: 128 rows x 8 c16
            int idx = tid + q * 512;
            int row = idx >> 3, c16 = idx & 7;
            size_t ar;
            if (MODE == 0) {
                int sp = (j * WIN + row + SHIFT) & (SLEN - 1);   // roll(-shift)
                ar = abase + (size_t)sp * DMODEL + g + c16 * 8;
            } else {
                ar = abase + (size_t)row * DMODEL + g + c16 * 8;
            }
            CP_ASYNC16(sbase + (uint32_t)(row * 144 + c16 * 16), Asrc_h + ar);
        }
#pragma unroll
        for (int q = 0; q < 4; q++) {          // B: 256 rows x 8 c16
            int idx = tid + q * 512;
            int row = idx >> 3, c16 = idx & 7;
            size_t br = (size_t)(n0 + row) * DMODEL + g + c16 * 8;
            CP_ASYNC16(sbase + 18432 + (uint32_t)(row * 144 + c16 * 16), Bsrc_h + br);
        }
        CP_COMMIT();
    };

    load_chunk(0, 0);
    load_chunk(1, 1);

    for (int c = 0; c < 8; c++) {
        if (c < 7) CP_WAIT(1); else CP_WAIT(0);
        __syncthreads();
        if (c + 2 < 8) load_chunk(c + 2, (c + 2) % 3);

        const __half* Ah = (const __half*)(smem + (c % 3) * STG_BYTES);
        const __half* Bh = Ah + 9216;
#pragma unroll
        for (int ks = 0; ks < 4; ks++) {
            HA ah[2];
#pragma unroll
            for (int i = 0; i < 2; i++)
                wmma::load_matrix_sync(ah[i], Ah + (wr * 32 + i * 16) * 72 + ks * 16, 72);
#pragma unroll
            for (int jj = 0; jj < 4; jj++) {
                HBc bh;
                wmma::load_matrix_sync(bh, Bh + (wc * 64 + jj * 16) * 72 + ks * 16, 72);
#pragma unroll
                for (int i = 0; i < 2; i++)
                    wmma::mma_sync(acc[i][jj], ah[i], bh, acc[i][jj]);
            }
        }
    }
    __syncthreads();

#pragma unroll
    for (int i = 0; i < 2; i++)
#pragma unroll
        for (int jj = 0; jj < 4; jj++)
            wmma::store_matrix_sync(Cs + (wr * 32 + i * 16) * 264 + wc * 64 + jj * 16,
                                    acc[i][jj], 264, wmma::mem_row_major);
    __syncthreads();

#pragma unroll
    for (int it = 0; it < 16; it++) {
        int idx = tid + it * 512;
        int r = idx >> 6, cc = (idx & 63) * 4;
        float4 v;
        v.x = Cs[r * 264 + cc + 0] + bias[n0 + cc + 0];
        v.y = Cs[r * 264 + cc + 1] + bias[n0 + cc + 1];
        v.z = Cs[r * 264 + cc + 2] + bias[n0 + cc + 2];
        v.w = Cs[r * 264 + cc + 3] + bias[n0 + cc + 3];
        if (MODE == 0) {
            int gc = n0 + cc;
            int p = gc >> 9, hh = (gc >> 6) & 7, d = gc & 63;
            size_t o = ((((size_t)p * NWIN + w) * NHEADS + hh) * WIN + r) * HD + d;
            hi_store4(v, g_qkv_hi + o);
        } else {
            int sp = (j * WIN + r + SHIFT) & (SLEN - 1);   // roll(+shift)
            *(float4*)(outp + ((size_t)b * SLEN + sp) * DMODEL + n0 + cc) = v;
        }
    }
}

// ---------------------------------------------------------------------------
// Attention (hi-only, full window, K/V read once, row-overlay smem; R12
// structure). NEW: loads via cp.async in two commit groups — Q+K first
// (waited before S), V second (waited only before PV, hidden behind
// S + softmax).
//
// smem map:
//   Ps region: 128 rows x 560 B (stride 140 floats) = 71680 B. Tenants:
//     - Qh [128][72] fp16 at byte 0      (dead after S phase)
//     - Kh [128][72] fp16 at byte 18432  (dead after S phase)
//     - Ps fp32 row r: floats [r*140, r*140+128)
//     - Ph fp16 row r: bytes  [r*560, r*560+256)   (row-exclusive overlay)
//     - Os fp32 row r: floats [r*140+72, r*140+140)
//   Vh [128][72] fp16 at 71680
// total 90112 B -> 2 CTAs/SM.
// ---------------------------------------------------------------------------
#define ATTN_SMEM 90112

__global__ __launch_bounds__(256, 2) void k_attn() {
    extern __shared__ char sm[];
    const uint32_t sb = smem_to_u32(sm);
    __half* Qh = (__half*)sm;                  // [128][72]
    __half* Kh = (__half*)(sm + 18432);        // [128][72]
    float*  Ps = (float*)sm;                   // stride 140 floats
    __half* Ph = (__half*)sm;                  // stride 280 halves, 128 used
    float*  Os = (float*)sm;                   // row r at r*140+72
    __half* Vh = (__half*)(sm + 71680);        // [128][72]

    const int h = blockIdx.x, w = blockIdx.y;
    const int tid = threadIdx.x;
    const int warp = tid >> 5, lane = tid & 31;

    const size_t part = (size_t)NWIN * NHEADS * WIN * HD;
    const size_t bq = ((size_t)w * NHEADS + h) * (WIN * HD);

    {   // cp.async loads: 2 threads per row, 32 halves (4 x 16B) per array.
        // Group 1: Q + K (needed for S). Group 2: V (needed only for PV).
        const int r = tid >> 1;
        const int cgb = (tid & 1) * 64;                 // byte offset within row
        const size_t so = bq + (size_t)r * HD + (tid & 1) * 32;
        const uint32_t rb = (uint32_t)(r * 144 + cgb);
#pragma unroll
        for (int q = 0; q < 4; q++) {
            CP_ASYNC16(sb + rb + q * 16,         g_qkv_hi + so + q * 8);          // Q
            CP_ASYNC16(sb + 18432 + rb + q * 16, g_qkv_hi + part + so + q * 8);   // K
        }
        CP_COMMIT();
#pragma unroll
        for (int q = 0; q < 4; q++)
            CP_ASYNC16(sb + 71680 + rb + q * 16, g_qkv_hi + 2 * part + so + q * 8); // V
        CP_COMMIT();
    }
    CP_WAIT(1);          // Q + K landed; V may still be in flight
    __syncthreads();

    // ---- S = Q K^T / 8 : 8 warps, 4x2 grid, 32x64 tiles ----
    {
        const int wrS = warp >> 1, wcS = warp & 1;
        CF sacc[2][4];
#pragma unroll
        for (int i = 0; i < 2; i++)
#pragma unroll
            for (int jj = 0; jj < 4; jj++) wmma::fill_fragment(sacc[i][jj], 0.0f);
#pragma unroll
        for (int kk = 0; kk < 4; kk++) {
            HA qh2[2];
#pragma unroll
            for (int i = 0; i < 2; i++)
                wmma::load_matrix_sync(qh2[i], Qh + (wrS * 32 + i * 16) * 72 + kk * 16, 72);
#pragma unroll
            for (int jj = 0; jj < 4; jj++) {
                HBc kh2;
                wmma::load_matrix_sync(kh2, Kh + (wcS * 64 + jj * 16) * 72 + kk * 16, 72);
#pragma unroll
                for (int i = 0; i < 2; i++)
                    wmma::mma_sync(sacc[i][jj], qh2[i], kh2, sacc[i][jj]);
            }
        }
        __syncthreads();   // ALL warps' Q/K reads done before Ps overlays them
#pragma unroll
        for (int i = 0; i < 2; i++)
#pragma unroll
            for (int jj = 0; jj < 4; jj++) {
#pragma unroll
                for (int e = 0; e < sacc[i][jj].num_elements; e++) sacc[i][jj].x[e] *= 0.125f;
                wmma::store_matrix_sync(Ps + (wrS * 32 + i * 16) * 140 + wcS * 64 + jj * 16,
                                        sacc[i][jj], 140, wmma::mem_row_major);
            }
    }
    __syncthreads();

    // ---- softmax: 8 warps x 16 rows; reads own Ps row into regs, THEN
    //      writes fp16 Ph into the head of the same row (row-exclusive) ----
#pragma unroll
    for (int rr = 0; rr < 16; rr++) {
        const int row = warp * 16 + rr;
        const float* prow = Ps + row * 140;
        float v0 = prow[lane], v1 = prow[lane + 32], v2 = prow[lane + 64], v3 = prow[lane + 96];
        float m = fmaxf(fmaxf(v0, v1), fmaxf(v2, v3));
#pragma unroll
        for (int o = 16; o; o >>= 1) m = fmaxf(m, __shfl_xor_sync(0xffffffffu, m, o));
        v0 = __expf(v0 - m); v1 = __expf(v1 - m); v2 = __expf(v2 - m); v3 = __expf(v3 - m);
        float s = v0 + v1 + v2 + v3;
#pragma unroll
        for (int o = 16; o; o >>= 1) s += __shfl_xor_sync(0xffffffffu, s, o);
        float inv = 1.0f / s;
        __half* ph = Ph + row * 280;
        ph[lane]      = __float2half_rn(v0 * inv);
        ph[lane + 32] = __float2half_rn(v1 * inv);
        ph[lane + 64] = __float2half_rn(v2 * inv);
        ph[lane + 96] = __float2half_rn(v3 * inv);
    }
    CP_WAIT(0);          // V landed (own-thread groups drained)
    __syncthreads();     // cross-thread visibility of V + Ph

    // ---- O = P V : 8 warps, one 16x64 tile each ----
    {
        CF oacc[4];
#pragma unroll
        for (int jj = 0; jj < 4; jj++) wmma::fill_fragment(oacc[jj], 0.0f);
#pragma unroll
        for (int kk = 0; kk < 8; kk++) {
            HA ph2;
            wmma::load_matrix_sync(ph2, Ph + (warp * 16) * 280 + kk * 16, 280);
#pragma unroll
            for (int jj = 0; jj < 4; jj++) {
                HBr vh2;
                wmma::load_matrix_sync(vh2, Vh + (kk * 16) * 72 + jj * 16, 72);
                wmma::mma_sync(oacc[jj], ph2, vh2, oacc[jj]);
            }
        }
        // Os bytes [288,560) per row are disjoint from Ph bytes [0,256);
        // Vh untouched. Sync before cross-region stores.
        __syncthreads();
#pragma unroll
        for (int jj = 0; jj < 4; jj++)
            wmma::store_matrix_sync(Os + (warp * 16) * 140 + 72 + jj * 16,
                                    oacc[jj], 140, wmma::mem_row_major);
    }
    __syncthreads();

    // ---- store O (hi only) ----
#pragma unroll
    for (int it = 0; it < 8; it++) {
        int idx = tid + it * 256;          // 128 rows x 16 col-groups
        int r = idx >> 4, cc = (idx & 15) * 4;
        float4 v;
        v.x = Os[r * 140 + 72 + cc + 0];
        v.y = Os[r * 140 + 72 + cc + 1];
        v.z = Os[r * 140 + 72 + cc + 2];
        v.w = Os[r * 140 + 72 + cc + 3];
        size_t o = ((size_t)w * WIN + r) * DMODEL + h * HD + cc;
        hi_store4(v, g_o_hi + o);
    }
}

// ---------------------------------------------------------------------------
extern "C" void kernel_launch(void* const* d_in, const int* in_sizes, int n_in,
                              void* d_out, int out_size) {
    const float* x     = (const float*)d_in[0];
    const float* w_in  = (const float*)d_in[1];
    const float* b_in  = (const float*)d_in[2];
    const float* w_out = (const float*)d_in[3];
    const float* b_out = (const float*)d_in[4];
    float* out = (float*)d_out;

    cudaFuncSetAttribute(k_proj<0>, cudaFuncAttributeMaxDynamicSharedMemorySize, PROJ_SMEM);
    cudaFuncSetAttribute(k_proj<1>, cudaFuncAttributeMaxDynamicSharedMemorySize, PROJ_SMEM);
    cudaFuncSetAttribute(k_attn,    cudaFuncAttributeMaxDynamicSharedMemorySize, ATTN_SMEM);

    k_split_all<<<(N4ALL + 255) / 256, 256>>>((const float4*)x, (const float4*)w_in,
                                              (const float4*)w_out);

    k_proj<0><<<dim3(6, NWIN), 512, PROJ_SMEM>>>(b_in, nullptr);
    k_attn<<<dim3(NHEADS, NWIN), 256, ATTN_SMEM>>>();
    k_proj<1><<<dim3(2, NWIN), 512, PROJ_SMEM>>>(b_out, out);
}

// round 14
// speedup vs baseline: 1.2308x; 1.1447x over previous
#include <cuda_runtime.h>
#include <cuda_fp16.h>
#include <mma.h>
#include <cstdint>
using namespace nvcuda;

// Problem constants (fixed by setup_inputs)
#define BATCH   32
#define SLEN    4096
#define DMODEL  512
#define NHEADS  8
#define HD      64
#define WIN     128
#define SHIFT   64
#define NWIN    1024          // total windows (BATCH * 32)

// ---------------------------------------------------------------------------
// Persistent fp16 arrays — all hi-only (calibrated rel_err ~7.0e-4).
// ---------------------------------------------------------------------------
__device__ __align__(16) __half g_x_hi[(size_t)BATCH * SLEN * DMODEL];
__device__ __align__(16) __half g_win_hi[3 * DMODEL * DMODEL];
__device__ __align__(16) __half g_wout_hi[DMODEL * DMODEL];
__device__ __align__(16) __half g_qkv_hi[(size_t)3 * NWIN * NHEADS * WIN * HD];
__device__ __align__(16) __half g_o_hi[(size_t)NWIN * WIN * DMODEL];

// ---------------------------------------------------------------------------
// wmma fp16 types (projections only)
// ---------------------------------------------------------------------------
using HA  = wmma::fragment<wmma::matrix_a, 16, 16, 16, __half, wmma::row_major>;
using HBc = wmma::fragment<wmma::matrix_b, 16, 16, 16, __half, wmma::col_major>;
using CF  = wmma::fragment<wmma::accumulator, 16, 16, 16, float>;

__device__ __forceinline__ void hi_store4(const float4 v, __half* hi) {
    *reinterpret_cast<__half2*>(hi)     = __halves2half2(__float2half_rn(v.x), __float2half_rn(v.y));
    *reinterpret_cast<__half2*>(hi + 2) = __halves2half2(__float2half_rn(v.z), __float2half_rn(v.w));
}

// ---------------------------------------------------------------------------
// PTX helpers
// ---------------------------------------------------------------------------
__device__ __forceinline__ uint32_t smem_to_u32(const void* p) {
    uint32_t a;
    asm("{ .reg .u64 t; cvta.to.shared.u64 t, %1; cvt.u32.u64 %0, t; }" : "=r"(a) : "l"(p));
    return a;
}
#define CP_ASYNC16(su32, gptr) \
    asm volatile("cp.async.cg.shared.global [%0], [%1], 16;" :: "r"(su32), "l"(gptr) : "memory")
#define CP_COMMIT() asm volatile("cp.async.commit_group;" ::: "memory")
#define CP_WAIT(n)  asm volatile("cp.async.wait_group %0;" :: "n"(n) : "memory")

__device__ __forceinline__ void mma16816(float c[4], uint32_t a0, uint32_t a1,
                                         uint32_t a2, uint32_t a3,
                                         uint32_t b0, uint32_t b1) {
    asm volatile(
        "mma.sync.aligned.m16n8k16.row.col.f32.f16.f16.f32 "
        "{%0,%1,%2,%3}, {%4,%5,%6,%7}, {%8,%9}, {%0,%1,%2,%3};"
        : "+f"(c[0]), "+f"(c[1]), "+f"(c[2]), "+f"(c[3])
        : "r"(a0), "r"(a1), "r"(a2), "r"(a3), "r"(b0), "r"(b1));
}
__device__ __forceinline__ void ldmx2t(uint32_t& r0, uint32_t& r1, uint32_t saddr) {
    asm volatile("ldmatrix.sync.aligned.m8n8.x2.trans.shared.b16 {%0,%1}, [%2];"
                 : "=r"(r0), "=r"(r1) : "r"(saddr));
}

// ---------------------------------------------------------------------------
// Prep splits, single merged launch over x ++ w_in ++ w_out (all hi-only).
// ---------------------------------------------------------------------------
#define N4X  (BATCH * SLEN * DMODEL / 4)        // 16,777,216
#define N4WI (3 * DMODEL * DMODEL / 4)          // 196,608
#define N4WO (DMODEL * DMODEL / 4)              // 65,536
#define N4ALL (N4X + N4WI + N4WO)

__global__ void k_split_all(const float4* __restrict__ x,
                            const float4* __restrict__ w_in,
                            const float4* __restrict__ w_out) {
    int i = blockIdx.x * blockDim.x + threadIdx.x;
    if (i >= N4ALL) return;
    if (i < N4X) {
        hi_store4(x[i], g_x_hi + (size_t)i * 4);
    } else if (i < N4X + N4WI) {
        int k = i - N4X;
        hi_store4(w_in[k], g_win_hi + (size_t)k * 4);
    } else {
        int k = i - N4X - N4WI;
        hi_store4(w_out[k], g_wout_hi + (size_t)k * 4);
    }
}

// ---------------------------------------------------------------------------
// Projection GEMM (frozen R7/R9 config): C[128x256] per CTA = Ah@Bh^T,
// cp.async 3-stage, 512 threads, warp grid 4x4, warp tile 32x64.
// MODE 0: A = rolled x, B = w_in -> g_qkv_hi, +b_in
// MODE 1: A = g_o_hi,  B = w_out -> fp32 out with roll(+shift), +b_out
// ---------------------------------------------------------------------------
#define STG_BYTES 55296
#define PROJ_SMEM (3 * STG_BYTES)

template <int MODE>
__global__ __launch_bounds__(512, 1) void k_proj(const float* __restrict__ bias,
                                                 float* __restrict__ outp) {
    extern __shared__ char smem[];
    const uint32_t sb0 = smem_to_u32(smem);
    float* Cs = (float*)smem;              // [128][264]

    const int tid  = threadIdx.x;
    const int warp = tid >> 5;
    const int wr = warp >> 2, wc = warp & 3;
    const int n0 = blockIdx.x * 256;
    const int w  = blockIdx.y;
    const int b  = w >> 5, j = w & 31;

    const __half* Asrc_h = (MODE == 0) ? g_x_hi : g_o_hi;
    const __half* Bsrc_h = (MODE == 0) ? g_win_hi : g_wout_hi;

    const size_t abase = (MODE == 0) ? ((size_t)b * SLEN) * DMODEL
                                     : ((size_t)w * WIN) * DMODEL;

    CF acc[2][4];
#pragma unroll
    for (int i = 0; i < 2; i++)
#pragma unroll
        for (int jj = 0; jj < 4; jj++) wmma::fill_fragment(acc[i][jj], 0.0f);

    auto load_chunk = [&](int c, int st) {
        const uint32_t sbase = sb0 + st * STG_BYTES;
        const size_t g = (size_t)c * 64;
#pragma unroll
        for (int q = 0; q < 2; q++) {          // A: 128 rows x 8 c16
            int idx = tid + q * 512;
            int row = idx >> 3, c16 = idx & 7;
            size_t ar;
            if (MODE == 0) {
                int sp = (j * WIN + row + SHIFT) & (SLEN - 1);   // roll(-shift)
                ar = abase + (size_t)sp * DMODEL + g + c16 * 8;
            } else {
                ar = abase + (size_t)row * DMODEL + g + c16 * 8;
            }
            CP_ASYNC16(sbase + (uint32_t)(row * 144 + c16 * 16), Asrc_h + ar);
        }
#pragma unroll
        for (int q = 0; q < 4; q++) {          // B: 256 rows x 8 c16
            int idx = tid + q * 512;
            int row = idx >> 3, c16 = idx & 7;
            size_t br = (size_t)(n0 + row) * DMODEL + g + c16 * 8;
            CP_ASYNC16(sbase + 18432 + (uint32_t)(row * 144 + c16 * 16), Bsrc_h + br);
        }
        CP_COMMIT();
    };

    load_chunk(0, 0);
    load_chunk(1, 1);

    for (int c = 0; c < 8; c++) {
        if (c < 7) CP_WAIT(1); else CP_WAIT(0);
        __syncthreads();
        if (c + 2 < 8) load_chunk(c + 2, (c + 2) % 3);

        const __half* Ah = (const __half*)(smem + (c % 3) * STG_BYTES);
        const __half* Bh = Ah + 9216;
#pragma unroll
        for (int ks = 0; ks < 4; ks++) {
            HA ah[2];
#pragma unroll
            for (int i = 0; i < 2; i++)
                wmma::load_matrix_sync(ah[i], Ah + (wr * 32 + i * 16) * 72 + ks * 16, 72);
#pragma unroll
            for (int jj = 0; jj < 4; jj++) {
                HBc bh;
                wmma::load_matrix_sync(bh, Bh + (wc * 64 + jj * 16) * 72 + ks * 16, 72);
#pragma unroll
                for (int i = 0; i < 2; i++)
                    wmma::mma_sync(acc[i][jj], ah[i], bh, acc[i][jj]);
            }
        }
    }
    __syncthreads();

#pragma unroll
    for (int i = 0; i < 2; i++)
#pragma unroll
        for (int jj = 0; jj < 4; jj++)
            wmma::store_matrix_sync(Cs + (wr * 32 + i * 16) * 264 + wc * 64 + jj * 16,
                                    acc[i][jj], 264, wmma::mem_row_major);
    __syncthreads();

#pragma unroll
    for (int it = 0; it < 16; it++) {
        int idx = tid + it * 512;
        int r = idx >> 6, cc = (idx & 63) * 4;
        float4 v;
        v.x = Cs[r * 264 + cc + 0] + bias[n0 + cc + 0];
        v.y = Cs[r * 264 + cc + 1] + bias[n0 + cc + 1];
        v.z = Cs[r * 264 + cc + 2] + bias[n0 + cc + 2];
        v.w = Cs[r * 264 + cc + 3] + bias[n0 + cc + 3];
        if (MODE == 0) {
            int gc = n0 + cc;
            int p = gc >> 9, hh = (gc >> 6) & 7, d = gc & 63;
            size_t o = ((((size_t)p * NWIN + w) * NHEADS + hh) * WIN + r) * HD + d;
            hi_store4(v, g_qkv_hi + o);
        } else {
            int sp = (j * WIN + r + SHIFT) & (SLEN - 1);   // roll(+shift)
            *(float4*)(outp + ((size_t)b * SLEN + sp) * DMODEL + n0 + cc) = v;
        }
    }
}

// ---------------------------------------------------------------------------
// Attention — register-resident softmax (PTX mma.m16n8k16, FA2-style).
// One CTA per (head, window), 256 threads (8 warps), 2 CTAs/SM.
// Warp w owns query rows 16w..16w+15 against all 128 keys.
//   S accumulators live in registers; softmax via 4-lane shfl; P packed to
//   f16x2 in registers (C-layout == next mma's A-layout); V via ldmatrix.trans.
// smem: Qh [128][72] @0, Kh @18432 B, Vh @36864 B — 55296 B total.
// Only 2 CTA-wide syncs (Q/K landed; V landed). O staged through dead Qh rows.
// ---------------------------------------------------------------------------
#define ATTN_SMEM 55296

__global__ __launch_bounds__(256, 2) void k_attn() {
    extern __shared__ __half smh[];
    __half* Qh = smh;              // [128][72] halves
    __half* Kh = smh + 9216;       // byte 18432
    const uint32_t sb = smem_to_u32(smh);
    const uint32_t vb = sb + 36864;    // Vh base (bytes)

    const int h = blockIdx.x, w = blockIdx.y;
    const int tid  = threadIdx.x;
    const int warp = tid >> 5, lane = tid & 31;
    const int gid = lane >> 2, tq = lane & 3;

    const size_t part = (size_t)NWIN * NHEADS * WIN * HD;
    const size_t bq = ((size_t)w * NHEADS + h) * (WIN * HD);

    {   // cp.async loads: 2 threads per row, 32 halves (4 x 16B) per array.
        const int r = tid >> 1;
        const uint32_t rb = (uint32_t)(r * 144 + (tid & 1) * 64);
        const size_t so = bq + (size_t)r * HD + (tid & 1) * 32;
#pragma unroll
        for (int q = 0; q < 4; q++) {
            CP_ASYNC16(sb + rb + q * 16,         g_qkv_hi + so + q * 8);          // Q
            CP_ASYNC16(sb + 18432 + rb + q * 16, g_qkv_hi + part + so + q * 8);   // K
        }
        CP_COMMIT();
#pragma unroll
        for (int q = 0; q < 4; q++)
            CP_ASYNC16(vb + rb + q * 16, g_qkv_hi + 2 * part + so + q * 8);       // V
        CP_COMMIT();
    }
    CP_WAIT(1);
    __syncthreads();           // Q + K visible; V still in flight

    // ---- S = Q K^T (rows 16w..16w+15 x 128 keys), fp32 regs ----
    const int r0 = warp * 16 + gid;
    uint32_t qa[4][4];
#pragma unroll
    for (int k = 0; k < 4; k++) {
        qa[k][0] = *(const uint32_t*)&Qh[(r0)     * 72 + k * 16 + tq * 2];
        qa[k][1] = *(const uint32_t*)&Qh[(r0 + 8) * 72 + k * 16 + tq * 2];
        qa[k][2] = *(const uint32_t*)&Qh[(r0)     * 72 + k * 16 + 8 + tq * 2];
        qa[k][3] = *(const uint32_t*)&Qh[(r0 + 8) * 72 + k * 16 + 8 + tq * 2];
    }
    float sacc[16][4];
#pragma unroll
    for (int t = 0; t < 16; t++)
#pragma unroll
        for (int e = 0; e < 4; e++) sacc[t][e] = 0.0f;

#pragma unroll
    for (int jn = 0; jn < 16; jn++) {
        const int nr = jn * 8 + gid;
#pragma unroll
        for (int k = 0; k < 4; k++) {
            uint32_t b0 = *(const uint32_t*)&Kh[nr * 72 + k * 16 + tq * 2];
            uint32_t b1 = *(const uint32_t*)&Kh[nr * 72 + k * 16 + 8 + tq * 2];
            mma16816(sacc[jn], qa[k][0], qa[k][1], qa[k][2], qa[k][3], b0, b1);
        }
    }

    // ---- softmax (rows r0, r0+8), scale 0.125 pre-exp; 4-lane reductions ----
#pragma unroll
    for (int t = 0; t < 16; t++)
#pragma unroll
        for (int e = 0; e < 4; e++) sacc[t][e] *= 0.125f;

    float m0 = -1e30f, m1 = -1e30f;
#pragma unroll
    for (int t = 0; t < 16; t++) {
        m0 = fmaxf(m0, fmaxf(sacc[t][0], sacc[t][1]));
        m1 = fmaxf(m1, fmaxf(sacc[t][2], sacc[t][3]));
    }
    m0 = fmaxf(m0, __shfl_xor_sync(0xffffffffu, m0, 1));
    m0 = fmaxf(m0, __shfl_xor_sync(0xffffffffu, m0, 2));
    m1 = fmaxf(m1, __shfl_xor_sync(0xffffffffu, m1, 1));
    m1 = fmaxf(m1, __shfl_xor_sync(0xffffffffu, m1, 2));

    float s0 = 0.0f, s1 = 0.0f;
#pragma unroll
    for (int t = 0; t < 16; t++) {
        sacc[t][0] = __expf(sacc[t][0] - m0);
        sacc[t][1] = __expf(sacc[t][1] - m0);
        sacc[t][2] = __expf(sacc[t][2] - m1);
        sacc[t][3] = __expf(sacc[t][3] - m1);
        s0 += sacc[t][0] + sacc[t][1];
        s1 += sacc[t][2] + sacc[t][3];
    }
    s0 += __shfl_xor_sync(0xffffffffu, s0, 1);
    s0 += __shfl_xor_sync(0xffffffffu, s0, 2);
    s1 += __shfl_xor_sync(0xffffffffu, s1, 1);
    s1 += __shfl_xor_sync(0xffffffffu, s1, 2);
    const float inv0 = 1.0f / s0, inv1 = 1.0f / s1;

    uint32_t ph0[16], ph1[16];     // P as f16x2; C-layout == A-layout of PV mma
#pragma unroll
    for (int t = 0; t < 16; t++) {
        __half2 p0 = __floats2half2_rn(sacc[t][0] * inv0, sacc[t][1] * inv0);
        __half2 p1 = __floats2half2_rn(sacc[t][2] * inv1, sacc[t][3] * inv1);
        ph0[t] = *reinterpret_cast<uint32_t*>(&p0);
        ph1[t] = *reinterpret_cast<uint32_t*>(&p1);
    }

    CP_WAIT(0);
    __syncthreads();           // V visible to all warps

    // ---- O = P V : 8 k-steps (k16) x 8 n8-tiles; V via ldmatrix.x2.trans ----
    float oacc[8][4];
#pragma unroll
    for (int jn = 0; jn < 8; jn++)
#pragma unroll
        for (int e = 0; e < 4; e++) oacc[jn][e] = 0.0f;

    const int ll = lane & 15;
#pragma unroll
    for (int kk = 0; kk < 8; kk++) {
        const uint32_t a0 = ph0[2 * kk],     a1 = ph1[2 * kk];
        const uint32_t a2 = ph0[2 * kk + 1], a3 = ph1[2 * kk + 1];
        const uint32_t rowa = vb + (uint32_t)((kk * 16 + ll) * 144);
#pragma unroll
        for (int jn = 0; jn < 8; jn++) {
            uint32_t b0, b1;
            ldmx2t(b0, b1, rowa + jn * 16);
            mma16816(oacc[jn], a0, a1, a2, a3, b0, b1);
        }
    }

    // ---- stage O into (dead, warp-private) Qh rows, then coalesced store ----
#pragma unroll
    for (int jn = 0; jn < 8; jn++) {
        __half2 o0 = __floats2half2_rn(oacc[jn][0], oacc[jn][1]);
        __half2 o1 = __floats2half2_rn(oacc[jn][2], oacc[jn][3]);
        *(__half2*)&Qh[(r0)     * 72 + jn * 8 + tq * 2] = o0;
        *(__half2*)&Qh[(r0 + 8) * 72 + jn * 8 + tq * 2] = o1;
    }
    __syncwarp();

    const size_t obase = ((size_t)w * WIN + warp * 16) * DMODEL + h * HD;
#pragma unroll
    for (int it = 0; it < 4; it++) {
        int idx = lane + it * 32;          // 16 rows x 8 chunks of 16B
        int r = idx >> 3, ch = idx & 7;
        uint4 v = *(const uint4*)&Qh[(warp * 16 + r) * 72 + ch * 8];
        *(uint4*)(g_o_hi + obase + (size_t)r * DMODEL + ch * 8) = v;
    }
}

// ---------------------------------------------------------------------------
extern "C" void kernel_launch(void* const* d_in, const int* in_sizes, int n_in,
                              void* d_out, int out_size) {
    const float* x     = (const float*)d_in[0];
    const float* w_in  = (const float*)d_in[1];
    const float* b_in  = (const float*)d_in[2];
    const float* w_out = (const float*)d_in[3];
    const float* b_out = (const float*)d_in[4];
    float* out = (float*)d_out;

    cudaFuncSetAttribute(k_proj<0>, cudaFuncAttributeMaxDynamicSharedMemorySize, PROJ_SMEM);
    cudaFuncSetAttribute(k_proj<1>, cudaFuncAttributeMaxDynamicSharedMemorySize, PROJ_SMEM);
    cudaFuncSetAttribute(k_attn,    cudaFuncAttributeMaxDynamicSharedMemorySize, ATTN_SMEM);

    k_split_all<<<(N4ALL + 255) / 256, 256>>>((const float4*)x, (const float4*)w_in,
                                              (const float4*)w_out);

    k_proj<0><<<dim3(6, NWIN), 512, PROJ_SMEM>>>(b_in, nullptr);
    k_attn<<<dim3(NHEADS, NWIN), 256, ATTN_SMEM>>>();
    k_proj<1><<<dim3(2, NWIN), 512, PROJ_SMEM>>>(b_out, out);
}